// round 1
// baseline (speedup 1.0000x reference)
#include <cuda_runtime.h>
#include <math.h>

#define N_NODES 50000
#define N_EDGES 800000
#define DIM     128
#define NHEAD   8
#define HDIM    16

// ---------------- scratch (no allocations allowed) ----------------
__device__ __align__(16) float g_hsrc[N_NODES * DIM];
__device__ __align__(16) float g_hdst[N_NODES * DIM];
__device__ __align__(16) float g_s[N_EDGES * NHEAD];
__device__ __align__(16) float g_m[N_NODES * NHEAD];
__device__ __align__(16) float g_denom[N_NODES * NHEAD];
__device__ __align__(16) float g_agg[N_NODES * DIM];

__device__ __forceinline__ float lrelu(float v) {
    return v > 0.f ? v : 0.2f * v;
}

__device__ __forceinline__ void atomicMaxFloat(float* addr, float v) {
    // standard monotonic-bits trick; correct for mixed signs
    if (v >= 0.f) atomicMax((int*)addr, __float_as_int(v));
    else          atomicMin((unsigned int*)addr, __float_as_uint(v));
}

// ---------------- init: m=-inf, denom=0, agg=0 ----------------
__global__ void k_init() {
    int i = blockIdx.x * blockDim.x + threadIdx.x;
    if (i < N_NODES * NHEAD) {
        g_m[i] = -INFINITY;
        g_denom[i] = 0.f;
    }
    if (i < N_NODES * DIM) g_agg[i] = 0.f;
}

// ---------------- GEMM1: h_src = x@W_src, h_dst = x@W_dst ----------------
// W-stationary: whole [128 x 256] concatenated weight in smem (128KB),
// 32-row chunks, 4 teams of 64 threads, each thread computes 4 cols x 8 rows.
__global__ void k_gemm1(const float* __restrict__ x,
                        const float* __restrict__ Wsrc,
                        const float* __restrict__ Wdst) {
    extern __shared__ float sm[];
    float* Wsm = sm;              // [128][256]
    float* xs  = sm + 128 * 256;  // [32][128]
    const int tid = threadIdx.x;

    // load weights (coalesced float4)
    for (int i = tid; i < 128 * 128 / 4; i += 256) {
        int k = i >> 5;
        int j = (i & 31) << 2;
        *((float4*)&Wsm[k * 256 + j])       = ((const float4*)Wsrc)[i];
        *((float4*)&Wsm[k * 256 + 128 + j]) = ((const float4*)Wdst)[i];
    }
    __syncthreads();

    const int team = tid >> 6;  // 0..3 (2 warps each)
    const int t    = tid & 63;  // col group: cols 4t..4t+3 of 256

    for (int r0 = blockIdx.x * 32; r0 < N_NODES; r0 += gridDim.x * 32) {
        __syncthreads();  // protect xs from previous iteration readers
        int rows = N_NODES - r0;
        if (rows > 32) rows = 32;
        for (int i = tid; i < rows * 32; i += 256)
            ((float4*)xs)[i] = ((const float4*)(x + (size_t)r0 * DIM))[i];
        __syncthreads();

        float acc[8][4];
#pragma unroll
        for (int j = 0; j < 8; j++)
#pragma unroll
            for (int c = 0; c < 4; c++) acc[j][c] = 0.f;

        for (int k = 0; k < 128; k += 4) {
            float4 w0 = *((float4*)&Wsm[(k + 0) * 256 + 4 * t]);
            float4 w1 = *((float4*)&Wsm[(k + 1) * 256 + 4 * t]);
            float4 w2 = *((float4*)&Wsm[(k + 2) * 256 + 4 * t]);
            float4 w3 = *((float4*)&Wsm[(k + 3) * 256 + 4 * t]);
#pragma unroll
            for (int j = 0; j < 8; j++) {
                int row = team + 4 * j;
                float4 a = *((float4*)&xs[row * 128 + k]);
                acc[j][0] += a.x * w0.x + a.y * w1.x + a.z * w2.x + a.w * w3.x;
                acc[j][1] += a.x * w0.y + a.y * w1.y + a.z * w2.y + a.w * w3.y;
                acc[j][2] += a.x * w0.z + a.y * w1.z + a.z * w2.z + a.w * w3.z;
                acc[j][3] += a.x * w0.w + a.y * w1.w + a.z * w2.w + a.w * w3.w;
            }
        }
#pragma unroll
        for (int j = 0; j < 8; j++) {
            int row = team + 4 * j;
            if (row < rows) {
                float4 v = make_float4(acc[j][0], acc[j][1], acc[j][2], acc[j][3]);
                size_t gr = (size_t)(r0 + row) * DIM;
                if (t < 32) *((float4*)&g_hsrc[gr + 4 * t]) = v;
                else        *((float4*)&g_hdst[gr + 4 * (t - 32)]) = v;
            }
        }
    }
}

// ---------------- edge pass A: logits + segment max ----------------
// one warp per edge; lane covers 4 contiguous floats -> head = lane/4
__global__ void k_logits(const int* __restrict__ src, const int* __restrict__ dst,
                         const float* __restrict__ attn) {
    int gw = (blockIdx.x * blockDim.x + threadIdx.x) >> 5;
    if (gw >= N_EDGES) return;
    int lane = threadIdx.x & 31;
    int s = src[gw], d = dst[gw];

    float4 a  = *((const float4*)&g_hsrc[(size_t)s * DIM + 4 * lane]);
    float4 bv = *((const float4*)&g_hdst[(size_t)d * DIM + 4 * lane]);
    float4 w  = ((const float4*)attn)[lane];

    float p = lrelu(a.x + bv.x) * w.x + lrelu(a.y + bv.y) * w.y +
              lrelu(a.z + bv.z) * w.z + lrelu(a.w + bv.w) * w.w;
    p += __shfl_xor_sync(0xFFFFFFFFu, p, 1);
    p += __shfl_xor_sync(0xFFFFFFFFu, p, 2);

    if ((lane & 3) == 0) {
        int h = lane >> 2;
        g_s[(size_t)gw * NHEAD + h] = p;
        atomicMaxFloat(&g_m[(size_t)d * NHEAD + h], p);
    }
}

// ---------------- edge pass B: exp + segment sum ----------------
__global__ void k_exp(const int* __restrict__ dst) {
    int e = blockIdx.x * blockDim.x + threadIdx.x;
    if (e >= N_EDGES) return;
    int d = dst[e];
    float4 s0 = ((float4*)g_s)[e * 2];
    float4 s1 = ((float4*)g_s)[e * 2 + 1];
    float4 m0 = ((const float4*)g_m)[d * 2];
    float4 m1 = ((const float4*)g_m)[d * 2 + 1];
    s0.x = expf(s0.x - m0.x); s0.y = expf(s0.y - m0.y);
    s0.z = expf(s0.z - m0.z); s0.w = expf(s0.w - m0.w);
    s1.x = expf(s1.x - m1.x); s1.y = expf(s1.y - m1.y);
    s1.z = expf(s1.z - m1.z); s1.w = expf(s1.w - m1.w);
    ((float4*)g_s)[e * 2]     = s0;
    ((float4*)g_s)[e * 2 + 1] = s1;
    float* dn = &g_denom[(size_t)d * NHEAD];
    atomicAdd(dn + 0, s0.x); atomicAdd(dn + 1, s0.y);
    atomicAdd(dn + 2, s0.z); atomicAdd(dn + 3, s0.w);
    atomicAdd(dn + 4, s1.x); atomicAdd(dn + 5, s1.y);
    atomicAdd(dn + 6, s1.z); atomicAdd(dn + 7, s1.w);
}

// ---------------- edge pass C: alpha * h_src scatter-add ----------------
__global__ void k_scatter(const int* __restrict__ src, const int* __restrict__ dst) {
    int gw = (blockIdx.x * blockDim.x + threadIdx.x) >> 5;
    if (gw >= N_EDGES) return;
    int lane = threadIdx.x & 31;
    int s = src[gw], d = dst[gw];
    int h = lane >> 2;

    float alpha = g_s[(size_t)gw * NHEAD + h] /
                  (g_denom[(size_t)d * NHEAD + h] + 1e-8f);
    float4 hv = *((const float4*)&g_hsrc[(size_t)s * DIM + 4 * lane]);
    float* p = &g_agg[(size_t)d * DIM + 4 * lane];
    atomicAdd(p + 0, hv.x * alpha);
    atomicAdd(p + 1, hv.y * alpha);
    atomicAdd(p + 2, hv.z * alpha);
    atomicAdd(p + 3, hv.w * alpha);
}

// ---------------- GEMM2 + bias + residual + LayerNorm ----------------
// 8 teams (1 warp each), each thread owns 4 cols, 4 rows per team per chunk.
__global__ void k_out(const float* __restrict__ Wout, const float* __restrict__ bias,
                      const float* __restrict__ x, const float* __restrict__ gamma,
                      const float* __restrict__ beta, float* __restrict__ out) {
    extern __shared__ float sm[];
    float* Wsm = sm;              // [128][128]
    float* xs  = sm + 128 * 128;  // [32][128]
    const int tid = threadIdx.x;

    for (int i = tid; i < 128 * 128 / 4; i += 256) {
        int k = i >> 5;
        int j = (i & 31) << 2;
        *((float4*)&Wsm[k * 128 + j]) = ((const float4*)Wout)[i];
    }
    __syncthreads();

    const int team = tid >> 5;  // 0..7 (one warp)
    const int t    = tid & 31;  // cols 4t..4t+3

    float4 b4  = ((const float4*)bias)[t];
    float4 g4  = ((const float4*)gamma)[t];
    float4 be4 = ((const float4*)beta)[t];

    for (int r0 = blockIdx.x * 32; r0 < N_NODES; r0 += gridDim.x * 32) {
        __syncthreads();
        int rows = N_NODES - r0;
        if (rows > 32) rows = 32;
        for (int i = tid; i < rows * 32; i += 256)
            ((float4*)xs)[i] = ((const float4*)(g_agg + (size_t)r0 * DIM))[i];
        __syncthreads();

        float acc[4][4];
#pragma unroll
        for (int j = 0; j < 4; j++)
#pragma unroll
            for (int c = 0; c < 4; c++) acc[j][c] = 0.f;

        for (int k = 0; k < 128; k += 4) {
            float4 w0 = *((float4*)&Wsm[(k + 0) * 128 + 4 * t]);
            float4 w1 = *((float4*)&Wsm[(k + 1) * 128 + 4 * t]);
            float4 w2 = *((float4*)&Wsm[(k + 2) * 128 + 4 * t]);
            float4 w3 = *((float4*)&Wsm[(k + 3) * 128 + 4 * t]);
#pragma unroll
            for (int j = 0; j < 4; j++) {
                int row = team + 8 * j;
                float4 a = *((float4*)&xs[row * 128 + k]);
                acc[j][0] += a.x * w0.x + a.y * w1.x + a.z * w2.x + a.w * w3.x;
                acc[j][1] += a.x * w0.y + a.y * w1.y + a.z * w2.y + a.w * w3.y;
                acc[j][2] += a.x * w0.z + a.y * w1.z + a.z * w2.z + a.w * w3.z;
                acc[j][3] += a.x * w0.w + a.y * w1.w + a.z * w2.w + a.w * w3.w;
            }
        }

#pragma unroll
        for (int j = 0; j < 4; j++) {
            int row = team + 8 * j;
            if (row < rows) {  // uniform across the warp/team
                size_t gr = (size_t)(r0 + row);
                float4 xr = ((const float4*)x)[gr * 32 + t];
                float4 v;
                v.x = acc[j][0] + b4.x + xr.x;
                v.y = acc[j][1] + b4.y + xr.y;
                v.z = acc[j][2] + b4.z + xr.z;
                v.w = acc[j][3] + b4.w + xr.w;

                float sum = v.x + v.y + v.z + v.w;
                float sq  = v.x * v.x + v.y * v.y + v.z * v.z + v.w * v.w;
#pragma unroll
                for (int o = 16; o > 0; o >>= 1) {
                    sum += __shfl_xor_sync(0xFFFFFFFFu, sum, o);
                    sq  += __shfl_xor_sync(0xFFFFFFFFu, sq, o);
                }
                float mean = sum * (1.f / 128.f);
                float var  = sq * (1.f / 128.f) - mean * mean;
                float rstd = rsqrtf(var + 1e-5f);

                float4 o4;
                o4.x = (v.x - mean) * rstd * g4.x + be4.x;
                o4.y = (v.y - mean) * rstd * g4.y + be4.y;
                o4.z = (v.z - mean) * rstd * g4.z + be4.z;
                o4.w = (v.w - mean) * rstd * g4.w + be4.w;
                ((float4*)out)[gr * 32 + t] = o4;
            }
        }
    }
}

// ---------------- launch ----------------
extern "C" void kernel_launch(void* const* d_in, const int* in_sizes, int n_in,
                              void* d_out, int out_size) {
    const float* x     = (const float*)d_in[0];
    const int*   ei    = (const int*)d_in[1];
    const float* Wsrc  = (const float*)d_in[2];
    const float* Wdst  = (const float*)d_in[3];
    const float* attn  = (const float*)d_in[4];
    const float* Wout  = (const float*)d_in[5];
    const float* bias  = (const float*)d_in[6];
    const float* gamma = (const float*)d_in[7];
    const float* beta  = (const float*)d_in[8];
    float* out = (float*)d_out;
    const int* src = ei;
    const int* dst = ei + N_EDGES;

    static_assert(sizeof(float4) == 16, "");

    cudaFuncSetAttribute(k_gemm1, cudaFuncAttributeMaxDynamicSharedMemorySize,
                         (128 * 256 + 32 * 128) * 4);
    cudaFuncSetAttribute(k_out, cudaFuncAttributeMaxDynamicSharedMemorySize,
                         (128 * 128 + 32 * 128) * 4);

    k_init<<<(N_NODES * DIM + 255) / 256, 256>>>();
    k_gemm1<<<152, 256, (128 * 256 + 32 * 128) * 4>>>(x, Wsrc, Wdst);
    k_logits<<<(N_EDGES + 7) / 8, 256>>>(src, dst, attn);
    k_exp<<<(N_EDGES + 255) / 256, 256>>>(dst);
    k_scatter<<<(N_EDGES + 7) / 8, 256>>>(src, dst);
    k_out<<<152, 256, (128 * 128 + 32 * 128) * 4>>>(Wout, bias, x, gamma, beta, out);
}

// round 2
// speedup vs baseline: 1.7240x; 1.7240x over previous
#include <cuda_runtime.h>
#include <math.h>

#define N_NODES 50000
#define N_EDGES 800000
#define DIM     128
#define NHEAD   8
#define HDIM    16

// ---------------- scratch (no allocations allowed) ----------------
__device__ __align__(16) float g_hsrc[N_NODES * DIM];
__device__ __align__(16) float g_hdst[N_NODES * DIM];
__device__ __align__(16) float g_denom[N_NODES * NHEAD];
__device__ __align__(16) float g_agg[N_NODES * DIM];

__device__ __forceinline__ float lrelu(float v) {
    return v > 0.f ? v : 0.2f * v;
}

__device__ __forceinline__ void red_add_v4(float* p, float a, float b, float c, float d) {
    asm volatile("red.global.add.v4.f32 [%0], {%1, %2, %3, %4};"
                 :: "l"(__cvta_generic_to_global(p)),
                    "f"(a), "f"(b), "f"(c), "f"(d)
                 : "memory");
}

// ---------------- init: denom=0, agg=0 ----------------
__global__ void k_init() {
    int i = blockIdx.x * blockDim.x + threadIdx.x;
    if (i < N_NODES * NHEAD / 4) ((float4*)g_denom)[i] = make_float4(0.f, 0.f, 0.f, 0.f);
    if (i < N_NODES * DIM / 4)   ((float4*)g_agg)[i]   = make_float4(0.f, 0.f, 0.f, 0.f);
}

// ---------------- GEMM1: h_src = x@W_src, h_dst = x@W_dst ----------------
__global__ void k_gemm1(const float* __restrict__ x,
                        const float* __restrict__ Wsrc,
                        const float* __restrict__ Wdst) {
    extern __shared__ float sm[];
    float* Wsm = sm;              // [128][256]
    float* xs  = sm + 128 * 256;  // [32][128]
    const int tid = threadIdx.x;

    for (int i = tid; i < 128 * 128 / 4; i += 256) {
        int k = i >> 5;
        int j = (i & 31) << 2;
        *((float4*)&Wsm[k * 256 + j])       = ((const float4*)Wsrc)[i];
        *((float4*)&Wsm[k * 256 + 128 + j]) = ((const float4*)Wdst)[i];
    }
    __syncthreads();

    const int team = tid >> 6;  // 0..3
    const int t    = tid & 63;  // col group of 256

    for (int r0 = blockIdx.x * 32; r0 < N_NODES; r0 += gridDim.x * 32) {
        __syncthreads();
        int rows = N_NODES - r0;
        if (rows > 32) rows = 32;
        for (int i = tid; i < rows * 32; i += 256)
            ((float4*)xs)[i] = ((const float4*)(x + (size_t)r0 * DIM))[i];
        __syncthreads();

        float acc[8][4];
#pragma unroll
        for (int j = 0; j < 8; j++)
#pragma unroll
            for (int c = 0; c < 4; c++) acc[j][c] = 0.f;

        for (int k = 0; k < 128; k += 4) {
            float4 w0 = *((float4*)&Wsm[(k + 0) * 256 + 4 * t]);
            float4 w1 = *((float4*)&Wsm[(k + 1) * 256 + 4 * t]);
            float4 w2 = *((float4*)&Wsm[(k + 2) * 256 + 4 * t]);
            float4 w3 = *((float4*)&Wsm[(k + 3) * 256 + 4 * t]);
#pragma unroll
            for (int j = 0; j < 8; j++) {
                int row = team + 4 * j;
                float4 a = *((float4*)&xs[row * 128 + k]);
                acc[j][0] += a.x * w0.x + a.y * w1.x + a.z * w2.x + a.w * w3.x;
                acc[j][1] += a.x * w0.y + a.y * w1.y + a.z * w2.y + a.w * w3.y;
                acc[j][2] += a.x * w0.z + a.y * w1.z + a.z * w2.z + a.w * w3.z;
                acc[j][3] += a.x * w0.w + a.y * w1.w + a.z * w2.w + a.w * w3.w;
            }
        }
#pragma unroll
        for (int j = 0; j < 8; j++) {
            int row = team + 4 * j;
            if (row < rows) {
                float4 v = make_float4(acc[j][0], acc[j][1], acc[j][2], acc[j][3]);
                size_t gr = (size_t)(r0 + row) * DIM;
                if (t < 32) *((float4*)&g_hsrc[gr + 4 * t]) = v;
                else        *((float4*)&g_hdst[gr + 4 * (t - 32)]) = v;
            }
        }
    }
}

// ---------------- fused edge pass: logits + exp + scatter ----------------
// one warp per edge; lane covers 4 contiguous floats -> head = lane/4.
// alpha normalization is deferred to k_out (divide by denom there), so the
// exp-weighted message can be scattered immediately while h_src is in regs.
__global__ void k_edge(const int* __restrict__ src, const int* __restrict__ dst,
                       const float* __restrict__ attn) {
    int gw = (blockIdx.x * blockDim.x + threadIdx.x) >> 5;
    if (gw >= N_EDGES) return;
    int lane = threadIdx.x & 31;
    int s = src[gw], d = dst[gw];

    float4 a  = *((const float4*)&g_hsrc[(size_t)s * DIM + 4 * lane]);
    float4 bv = *((const float4*)&g_hdst[(size_t)d * DIM + 4 * lane]);
    float4 w  = ((const float4*)attn)[lane];

    float p = lrelu(a.x + bv.x) * w.x + lrelu(a.y + bv.y) * w.y +
              lrelu(a.z + bv.z) * w.z + lrelu(a.w + bv.w) * w.w;
    p += __shfl_xor_sync(0xFFFFFFFFu, p, 1);
    p += __shfl_xor_sync(0xFFFFFFFFu, p, 2);
    // logits are O(few): exp without max-shift is safe, ratios identical
    float e = __expf(p);

    // scatter exp-weighted message (vector reduction, 1 instr per lane)
    red_add_v4(&g_agg[(size_t)d * DIM + 4 * lane],
               a.x * e, a.y * e, a.z * e, a.w * e);

    // denominator: gather the 8 head exps into lanes 0 (heads 0-3) and 1 (4-7)
    int base = (lane & 1) << 4;
    float q0 = __shfl_sync(0xFFFFFFFFu, e, base + 0);
    float q1 = __shfl_sync(0xFFFFFFFFu, e, base + 4);
    float q2 = __shfl_sync(0xFFFFFFFFu, e, base + 8);
    float q3 = __shfl_sync(0xFFFFFFFFu, e, base + 12);
    if (lane < 2)
        red_add_v4(&g_denom[(size_t)d * NHEAD + 4 * lane], q0, q1, q2, q3);
}

// ---------------- GEMM2 + bias + residual + LayerNorm ----------------
// agg is divided by (denom + 1e-8) per head while staging into smem.
__global__ void k_out(const float* __restrict__ Wout, const float* __restrict__ bias,
                      const float* __restrict__ x, const float* __restrict__ gamma,
                      const float* __restrict__ beta, float* __restrict__ out) {
    extern __shared__ float sm[];
    float* Wsm = sm;              // [128][128]
    float* xs  = sm + 128 * 128;  // [32][128]
    const int tid = threadIdx.x;

    for (int i = tid; i < 128 * 128 / 4; i += 256) {
        int k = i >> 5;
        int j = (i & 31) << 2;
        *((float4*)&Wsm[k * 128 + j]) = ((const float4*)Wout)[i];
    }
    __syncthreads();

    const int team = tid >> 5;  // 0..7 (one warp)
    const int t    = tid & 31;  // cols 4t..4t+3

    float4 b4  = ((const float4*)bias)[t];
    float4 g4  = ((const float4*)gamma)[t];
    float4 be4 = ((const float4*)beta)[t];

    for (int r0 = blockIdx.x * 32; r0 < N_NODES; r0 += gridDim.x * 32) {
        __syncthreads();
        int rows = N_NODES - r0;
        if (rows > 32) rows = 32;
        for (int i = tid; i < rows * 32; i += 256) {
            int row = i >> 5;
            int cg  = i & 31;           // float4 index within row; head = cg>>2
            float4 v = ((const float4*)(g_agg + (size_t)r0 * DIM))[i];
            float dn = g_denom[(size_t)(r0 + row) * NHEAD + (cg >> 2)];
            float inv = 1.f / (dn + 1e-8f);
            v.x *= inv; v.y *= inv; v.z *= inv; v.w *= inv;
            ((float4*)xs)[i] = v;
        }
        __syncthreads();

        float acc[4][4];
#pragma unroll
        for (int j = 0; j < 4; j++)
#pragma unroll
            for (int c = 0; c < 4; c++) acc[j][c] = 0.f;

        for (int k = 0; k < 128; k += 4) {
            float4 w0 = *((float4*)&Wsm[(k + 0) * 128 + 4 * t]);
            float4 w1 = *((float4*)&Wsm[(k + 1) * 128 + 4 * t]);
            float4 w2 = *((float4*)&Wsm[(k + 2) * 128 + 4 * t]);
            float4 w3 = *((float4*)&Wsm[(k + 3) * 128 + 4 * t]);
#pragma unroll
            for (int j = 0; j < 4; j++) {
                int row = team + 8 * j;
                float4 a = *((float4*)&xs[row * 128 + k]);
                acc[j][0] += a.x * w0.x + a.y * w1.x + a.z * w2.x + a.w * w3.x;
                acc[j][1] += a.x * w0.y + a.y * w1.y + a.z * w2.y + a.w * w3.y;
                acc[j][2] += a.x * w0.z + a.y * w1.z + a.z * w2.z + a.w * w3.z;
                acc[j][3] += a.x * w0.w + a.y * w1.w + a.z * w2.w + a.w * w3.w;
            }
        }

#pragma unroll
        for (int j = 0; j < 4; j++) {
            int row = team + 8 * j;
            if (row < rows) {
                size_t gr = (size_t)(r0 + row);
                float4 xr = ((const float4*)x)[gr * 32 + t];
                float4 v;
                v.x = acc[j][0] + b4.x + xr.x;
                v.y = acc[j][1] + b4.y + xr.y;
                v.z = acc[j][2] + b4.z + xr.z;
                v.w = acc[j][3] + b4.w + xr.w;

                float sum = v.x + v.y + v.z + v.w;
                float sq  = v.x * v.x + v.y * v.y + v.z * v.z + v.w * v.w;
#pragma unroll
                for (int o = 16; o > 0; o >>= 1) {
                    sum += __shfl_xor_sync(0xFFFFFFFFu, sum, o);
                    sq  += __shfl_xor_sync(0xFFFFFFFFu, sq, o);
                }
                float mean = sum * (1.f / 128.f);
                float var  = sq * (1.f / 128.f) - mean * mean;
                float rstd = rsqrtf(var + 1e-5f);

                float4 o4;
                o4.x = (v.x - mean) * rstd * g4.x + be4.x;
                o4.y = (v.y - mean) * rstd * g4.y + be4.y;
                o4.z = (v.z - mean) * rstd * g4.z + be4.z;
                o4.w = (v.w - mean) * rstd * g4.w + be4.w;
                ((float4*)out)[gr * 32 + t] = o4;
            }
        }
    }
}

// ---------------- launch ----------------
extern "C" void kernel_launch(void* const* d_in, const int* in_sizes, int n_in,
                              void* d_out, int out_size) {
    const float* x     = (const float*)d_in[0];
    const int*   ei    = (const int*)d_in[1];
    const float* Wsrc  = (const float*)d_in[2];
    const float* Wdst  = (const float*)d_in[3];
    const float* attn  = (const float*)d_in[4];
    const float* Wout  = (const float*)d_in[5];
    const float* bias  = (const float*)d_in[6];
    const float* gamma = (const float*)d_in[7];
    const float* beta  = (const float*)d_in[8];
    float* out = (float*)d_out;
    const int* src = ei;
    const int* dst = ei + N_EDGES;

    cudaFuncSetAttribute(k_gemm1, cudaFuncAttributeMaxDynamicSharedMemorySize,
                         (128 * 256 + 32 * 128) * 4);
    cudaFuncSetAttribute(k_out, cudaFuncAttributeMaxDynamicSharedMemorySize,
                         (128 * 128 + 32 * 128) * 4);

    k_init<<<(N_NODES * DIM / 4 + 255) / 256, 256>>>();
    k_gemm1<<<152, 256, (128 * 256 + 32 * 128) * 4>>>(x, Wsrc, Wdst);
    k_edge<<<(N_EDGES + 7) / 8, 256>>>(src, dst, attn);
    k_out<<<152, 256, (128 * 128 + 32 * 128) * 4>>>(Wout, bias, x, gamma, beta, out);
}

// round 5
// speedup vs baseline: 2.4754x; 1.4358x over previous
#include <cuda_runtime.h>
#include <math.h>

#define N_NODES 50000
#define N_EDGES 800000
#define DIM     128
#define NHEAD   8

#define XPAD 132   // stride for A-operand smem: 132 % 32 == 4 -> conflict-free A frags
#define WPAD 136   // stride for B-operand smem: 136 % 32 == 8 -> conflict-free B frags

// ---------------- scratch ----------------
__device__ __align__(16) float g_hsrc[N_NODES * DIM];
__device__ __align__(16) float g_hdst[N_NODES * DIM];
__device__ __align__(16) float g_denom[N_NODES * NHEAD];
__device__ __align__(16) float g_agg[N_NODES * DIM];

__device__ __forceinline__ float lrelu(float v) { return v > 0.f ? v : 0.2f * v; }

__device__ __forceinline__ float f2tf(float x) {
    float y;
    asm("cvt.rna.tf32.f32 %0, %1;" : "=f"(y) : "f"(x));
    return y;
}

__device__ __forceinline__ void mma_tf32(float c[4], const unsigned a[4],
                                         unsigned b0, unsigned b1) {
    asm volatile(
        "mma.sync.aligned.m16n8k8.row.col.f32.tf32.tf32.f32 "
        "{%0,%1,%2,%3},{%4,%5,%6,%7},{%8,%9},{%0,%1,%2,%3};"
        : "+f"(c[0]), "+f"(c[1]), "+f"(c[2]), "+f"(c[3])
        : "r"(a[0]), "r"(a[1]), "r"(a[2]), "r"(a[3]), "r"(b0), "r"(b1));
}

__device__ __forceinline__ void red_add_v4(float* p, float a, float b, float c, float d) {
    asm volatile("red.global.add.v4.f32 [%0], {%1, %2, %3, %4};"
                 :: "l"(__cvta_generic_to_global(p)),
                    "f"(a), "f"(b), "f"(c), "f"(d)
                 : "memory");
}

// ---------------- init ----------------
__global__ void k_init() {
    int i = blockIdx.x * blockDim.x + threadIdx.x;
    if (i < N_NODES * NHEAD / 4) ((float4*)g_denom)[i] = make_float4(0.f, 0.f, 0.f, 0.f);
    if (i < N_NODES * DIM / 4)   ((float4*)g_agg)[i]   = make_float4(0.f, 0.f, 0.f, 0.f);
}

// ---------------- GEMM1 (tf32 HMMA): h = x @ W, grid.y picks src/dst ----------------
__global__ void __launch_bounds__(256, 2)
k_gemm1(const float* __restrict__ x,
        const float* __restrict__ Wsrc, const float* __restrict__ Wdst) {
    extern __shared__ float sm[];
    float* Wsm = sm;               // [128][WPAD]
    float* xs  = sm + 128 * WPAD;  // [64][XPAD]
    const int tid = threadIdx.x;

    const float* W = blockIdx.y ? Wdst : Wsrc;
    float* hout    = blockIdx.y ? g_hdst : g_hsrc;

    for (int i = tid; i < 128 * 32; i += 256) {
        int r = i >> 5, c4 = (i & 31) << 2;
        float4 v = ((const float4*)W)[i];
        float* p = &Wsm[r * WPAD + c4];
        p[0] = f2tf(v.x); p[1] = f2tf(v.y); p[2] = f2tf(v.z); p[3] = f2tf(v.w);
    }
    __syncthreads();

    const int warp = tid >> 5, lane = tid & 31;
    const int g = lane >> 2, t = lane & 3;
    const int m_off = (warp & 1) * 32;   // 2 warps in M
    const int n_off = (warp >> 1) * 32;  // 4 warps in N

    for (int r0 = blockIdx.x * 64; r0 < N_NODES; r0 += gridDim.x * 64) {
        __syncthreads();
        int rows = N_NODES - r0; if (rows > 64) rows = 64;
        for (int i = tid; i < rows * 32; i += 256) {
            int r = i >> 5, c4 = (i & 31) << 2;
            float4 v = ((const float4*)(x + (size_t)r0 * DIM))[i];
            float* p = &xs[r * XPAD + c4];
            p[0] = f2tf(v.x); p[1] = f2tf(v.y); p[2] = f2tf(v.z); p[3] = f2tf(v.w);
        }
        __syncthreads();

        float acc[2][4][4];
#pragma unroll
        for (int mt = 0; mt < 2; mt++)
#pragma unroll
            for (int j = 0; j < 4; j++)
#pragma unroll
                for (int c = 0; c < 4; c++) acc[mt][j][c] = 0.f;

#pragma unroll 4
        for (int k = 0; k < 128; k += 8) {
            unsigned a[2][4];
#pragma unroll
            for (int mt = 0; mt < 2; mt++) {
                int base = (m_off + mt * 16 + g) * XPAD + k + t;
                a[mt][0] = __float_as_uint(xs[base]);
                a[mt][1] = __float_as_uint(xs[base + 8 * XPAD]);
                a[mt][2] = __float_as_uint(xs[base + 4]);
                a[mt][3] = __float_as_uint(xs[base + 8 * XPAD + 4]);
            }
#pragma unroll
            for (int j = 0; j < 4; j++) {
                int n = n_off + 8 * j + g;
                unsigned b0 = __float_as_uint(Wsm[(k + t) * WPAD + n]);
                unsigned b1 = __float_as_uint(Wsm[(k + t + 4) * WPAD + n]);
                mma_tf32(acc[0][j], a[0], b0, b1);
                mma_tf32(acc[1][j], a[1], b0, b1);
            }
        }

#pragma unroll
        for (int mt = 0; mt < 2; mt++) {
            int rl = m_off + mt * 16 + g;
#pragma unroll
            for (int j = 0; j < 4; j++) {
                int n = n_off + 8 * j + 2 * t;
                if (rl < rows)
                    *(float2*)&hout[(size_t)(r0 + rl) * DIM + n] =
                        make_float2(acc[mt][j][0], acc[mt][j][1]);
                if (rl + 8 < rows)
                    *(float2*)&hout[(size_t)(r0 + rl + 8) * DIM + n] =
                        make_float2(acc[mt][j][2], acc[mt][j][3]);
            }
        }
    }
}

// ---------------- fused edge pass: logits + exp + scatter ----------------
__global__ void k_edge(const int* __restrict__ src, const int* __restrict__ dst,
                       const float* __restrict__ attn) {
    int gw = (blockIdx.x * blockDim.x + threadIdx.x) >> 5;
    if (gw >= N_EDGES) return;
    int lane = threadIdx.x & 31;
    int s = src[gw], d = dst[gw];

    float4 a  = *((const float4*)&g_hsrc[(size_t)s * DIM + 4 * lane]);
    float4 bv = *((const float4*)&g_hdst[(size_t)d * DIM + 4 * lane]);
    float4 w  = ((const float4*)attn)[lane];

    float p = lrelu(a.x + bv.x) * w.x + lrelu(a.y + bv.y) * w.y +
              lrelu(a.z + bv.z) * w.z + lrelu(a.w + bv.w) * w.w;
    p += __shfl_xor_sync(0xFFFFFFFFu, p, 1);
    p += __shfl_xor_sync(0xFFFFFFFFu, p, 2);
    float e = __expf(p);

    red_add_v4(&g_agg[(size_t)d * DIM + 4 * lane],
               a.x * e, a.y * e, a.z * e, a.w * e);

    int base = (lane & 1) << 4;
    float q0 = __shfl_sync(0xFFFFFFFFu, e, base + 0);
    float q1 = __shfl_sync(0xFFFFFFFFu, e, base + 4);
    float q2 = __shfl_sync(0xFFFFFFFFu, e, base + 8);
    float q3 = __shfl_sync(0xFFFFFFFFu, e, base + 12);
    if (lane < 2)
        red_add_v4(&g_denom[(size_t)d * NHEAD + 4 * lane], q0, q1, q2, q3);
}

// ---------------- GEMM2 (tf32 HMMA) + bias + residual + LayerNorm ----------------
__global__ void __launch_bounds__(256, 2)
k_out(const float* __restrict__ Wout, const float* __restrict__ bias,
      const float* __restrict__ x, const float* __restrict__ gamma,
      const float* __restrict__ beta, float* __restrict__ out) {
    extern __shared__ float sm[];
    float* Wsm = sm;               // [128][WPAD]
    float* xs  = sm + 128 * WPAD;  // [64][XPAD], reused for result tile
    const int tid = threadIdx.x;

    for (int i = tid; i < 128 * 32; i += 256) {
        int r = i >> 5, c4 = (i & 31) << 2;
        float4 v = ((const float4*)Wout)[i];
        float* p = &Wsm[r * WPAD + c4];
        p[0] = f2tf(v.x); p[1] = f2tf(v.y); p[2] = f2tf(v.z); p[3] = f2tf(v.w);
    }
    __syncthreads();

    const int warp = tid >> 5, lane = tid & 31;
    const int g = lane >> 2, t = lane & 3;
    const int m_off = (warp & 1) * 32;
    const int n_off = (warp >> 1) * 32;

    for (int r0 = blockIdx.x * 64; r0 < N_NODES; r0 += gridDim.x * 64) {
        __syncthreads();
        int rows = N_NODES - r0; if (rows > 64) rows = 64;
        // stage normalized messages: agg / (denom + 1e-8), tf32-rounded
        for (int i = tid; i < rows * 32; i += 256) {
            int r = i >> 5, c4 = (i & 31) << 2;  // head = c4 / 16
            float4 v = ((const float4*)(g_agg + (size_t)r0 * DIM))[i];
            float dn = g_denom[(size_t)(r0 + r) * NHEAD + (c4 >> 4)];
            float inv = 1.f / (dn + 1e-8f);
            float* p = &xs[r * XPAD + c4];
            p[0] = f2tf(v.x * inv); p[1] = f2tf(v.y * inv);
            p[2] = f2tf(v.z * inv); p[3] = f2tf(v.w * inv);
        }
        __syncthreads();

        float acc[2][4][4];
#pragma unroll
        for (int mt = 0; mt < 2; mt++)
#pragma unroll
            for (int j = 0; j < 4; j++)
#pragma unroll
                for (int c = 0; c < 4; c++) acc[mt][j][c] = 0.f;

#pragma unroll 4
        for (int k = 0; k < 128; k += 8) {
            unsigned a[2][4];
#pragma unroll
            for (int mt = 0; mt < 2; mt++) {
                int base = (m_off + mt * 16 + g) * XPAD + k + t;
                a[mt][0] = __float_as_uint(xs[base]);
                a[mt][1] = __float_as_uint(xs[base + 8 * XPAD]);
                a[mt][2] = __float_as_uint(xs[base + 4]);
                a[mt][3] = __float_as_uint(xs[base + 8 * XPAD + 4]);
            }
#pragma unroll
            for (int j = 0; j < 4; j++) {
                int n = n_off + 8 * j + g;
                unsigned b0 = __float_as_uint(Wsm[(k + t) * WPAD + n]);
                unsigned b1 = __float_as_uint(Wsm[(k + t + 4) * WPAD + n]);
                mma_tf32(acc[0][j], a[0], b0, b1);
                mma_tf32(acc[1][j], a[1], b0, b1);
            }
        }
        __syncthreads();  // xs readers done; reuse xs for result tile

#pragma unroll
        for (int mt = 0; mt < 2; mt++) {
            int rl = m_off + mt * 16 + g;
#pragma unroll
            for (int j = 0; j < 4; j++) {
                int n = n_off + 8 * j + 2 * t;
                xs[rl * XPAD + n]           = acc[mt][j][0];
                xs[rl * XPAD + n + 1]       = acc[mt][j][1];
                xs[(rl + 8) * XPAD + n]     = acc[mt][j][2];
                xs[(rl + 8) * XPAD + n + 1] = acc[mt][j][3];
            }
        }
        __syncthreads();

        // LN pass: 4 threads per row, 32 cols each
        {
            int row = tid >> 2, tr = tid & 3;
            if (row < rows) {
                size_t gr = (size_t)(r0 + row);
                float vals[8][4];
                float sum = 0.f, sq = 0.f;
#pragma unroll
                for (int c = 0; c < 8; c++) {
                    int col = tr * 32 + 4 * c;
                    float4 b4 = *((const float4*)&bias[col]);
                    float4 xr = *((const float4*)&x[gr * DIM + col]);
                    float* p = &xs[row * XPAD + col];
                    float v0 = p[0] + b4.x + xr.x;
                    float v1 = p[1] + b4.y + xr.y;
                    float v2 = p[2] + b4.z + xr.z;
                    float v3 = p[3] + b4.w + xr.w;
                    vals[c][0] = v0; vals[c][1] = v1; vals[c][2] = v2; vals[c][3] = v3;
                    sum += v0 + v1 + v2 + v3;
                    sq  += v0 * v0 + v1 * v1 + v2 * v2 + v3 * v3;
                }
                sum += __shfl_xor_sync(0xFFFFFFFFu, sum, 1);
                sum += __shfl_xor_sync(0xFFFFFFFFu, sum, 2);
                sq  += __shfl_xor_sync(0xFFFFFFFFu, sq, 1);
                sq  += __shfl_xor_sync(0xFFFFFFFFu, sq, 2);
                float mean = sum * (1.f / 128.f);
                float var  = sq * (1.f / 128.f) - mean * mean;
                float rstd = rsqrtf(var + 1e-5f);
#pragma unroll
                for (int c = 0; c < 8; c++) {
                    int col = tr * 32 + 4 * c;
                    float4 g4  = *((const float4*)&gamma[col]);
                    float4 be4 = *((const float4*)&beta[col]);
                    float4 o4;
                    o4.x = (vals[c][0] - mean) * rstd * g4.x + be4.x;
                    o4.y = (vals[c][1] - mean) * rstd * g4.y + be4.y;
                    o4.z = (vals[c][2] - mean) * rstd * g4.z + be4.z;
                    o4.w = (vals[c][3] - mean) * rstd * g4.w + be4.w;
                    *((float4*)&out[gr * DIM + col]) = o4;
                }
            }
        }
    }
}

// ---------------- launch ----------------
extern "C" void kernel_launch(void* const* d_in, const int* in_sizes, int n_in,
                              void* d_out, int out_size) {
    const float* x     = (const float*)d_in[0];
    const int*   ei    = (const int*)d_in[1];
    const float* Wsrc  = (const float*)d_in[2];
    const float* Wdst  = (const float*)d_in[3];
    const float* attn  = (const float*)d_in[4];
    const float* Wout  = (const float*)d_in[5];
    const float* bias  = (const float*)d_in[6];
    const float* gamma = (const float*)d_in[7];
    const float* beta  = (const float*)d_in[8];
    float* out = (float*)d_out;
    const int* src = ei;
    const int* dst = ei + N_EDGES;

    const int SMEM = (128 * WPAD + 64 * XPAD) * 4;  // ~103 KB

    cudaFuncSetAttribute(k_gemm1, cudaFuncAttributeMaxDynamicSharedMemorySize, SMEM);
    cudaFuncSetAttribute(k_out,   cudaFuncAttributeMaxDynamicSharedMemorySize, SMEM);

    const int TILES = (N_NODES + 63) / 64;  // 782

    k_init<<<(N_NODES * DIM / 4 + 255) / 256, 256>>>();
    k_gemm1<<<dim3(TILES, 2), 256, SMEM>>>(x, Wsrc, Wdst);
    k_edge<<<(N_EDGES + 7) / 8, 256>>>(src, dst, attn);
    k_out<<<TILES, 256, SMEM>>>(Wout, bias, x, gamma, beta, out);
}

// round 6
// speedup vs baseline: 3.0826x; 1.2453x over previous
#include <cuda_runtime.h>
#include <cuda_fp16.h>
#include <math.h>

#define N_NODES 50000
#define N_EDGES 800000
#define DIM     128
#define NHEAD   8

#define XPAD 132   // A-operand smem stride: 132 % 32 == 4 -> conflict-free A frags
#define WPAD 136   // B-operand smem stride: 136 % 32 == 8 -> conflict-free B frags

#define SCAN_BLOCKS ((N_NODES + 255) / 256)   // 196

// ---------------- scratch ----------------
__device__ __align__(16) __half g_hsrc[N_NODES * DIM];
__device__ __align__(16) __half g_hdst[N_NODES * DIM];
__device__ __align__(16) float  g_msg[N_NODES * DIM];     // normalized, tf32-rounded
__device__ int g_cnt[N_NODES];        // histogram, then fill cursor
__device__ int g_off[N_NODES + 1];    // CSR offsets by dst
__device__ int g_eid[N_EDGES];        // src node per CSR slot
__device__ int g_bsum[SCAN_BLOCKS];

__device__ __forceinline__ float lrelu(float v) { return fmaxf(v, 0.2f * v); }

__device__ __forceinline__ float f2tf(float x) {
    float y;
    asm("cvt.rna.tf32.f32 %0, %1;" : "=f"(y) : "f"(x));
    return y;
}

__device__ __forceinline__ void mma_tf32(float c[4], const unsigned a[4],
                                         unsigned b0, unsigned b1) {
    asm volatile(
        "mma.sync.aligned.m16n8k8.row.col.f32.tf32.tf32.f32 "
        "{%0,%1,%2,%3},{%4,%5,%6,%7},{%8,%9},{%0,%1,%2,%3};"
        : "+f"(c[0]), "+f"(c[1]), "+f"(c[2]), "+f"(c[3])
        : "r"(a[0]), "r"(a[1]), "r"(a[2]), "r"(a[3]), "r"(b0), "r"(b1));
}

// ---------------- CSR build ----------------
__global__ void k_zero() {
    int i = blockIdx.x * blockDim.x + threadIdx.x;
    if (i < N_NODES) g_cnt[i] = 0;
}

__global__ void k_hist(const int* __restrict__ dst) {
    int e = blockIdx.x * blockDim.x + threadIdx.x;
    if (e < N_EDGES) atomicAdd(&g_cnt[dst[e]], 1);
}

__device__ __forceinline__ int block_incl_scan(int c, int tid) {
    __shared__ int ws[8];
    int lane = tid & 31, wid = tid >> 5;
    int v = c;
#pragma unroll
    for (int o = 1; o < 32; o <<= 1) {
        int n = __shfl_up_sync(0xFFFFFFFFu, v, o);
        if (lane >= o) v += n;
    }
    if (lane == 31) ws[wid] = v;
    __syncthreads();
    if (wid == 0) {
        int t = (lane < 8) ? ws[lane] : 0;
#pragma unroll
        for (int o = 1; o < 8; o <<= 1) {
            int n = __shfl_up_sync(0xFFFFFFFFu, t, o);
            if (lane >= o) t += n;
        }
        if (lane < 8) ws[lane] = t;
    }
    __syncthreads();
    return v + (wid > 0 ? ws[wid - 1] : 0);
}

__global__ void k_scan1() {
    int tid = threadIdx.x;
    int idx = blockIdx.x * 256 + tid;
    int c = (idx < N_NODES) ? g_cnt[idx] : 0;
    int incl = block_incl_scan(c, tid);
    if (idx < N_NODES) g_off[idx] = incl - c;  // exclusive within block
    if (tid == 255) g_bsum[blockIdx.x] = incl;
}

__global__ void k_scan2() {
    int tid = threadIdx.x;
    int c = (tid < SCAN_BLOCKS) ? g_bsum[tid] : 0;
    int incl = block_incl_scan(c, tid);
    if (tid < SCAN_BLOCKS) g_bsum[tid] = incl - c;  // exclusive block offsets
    if (tid == 0) g_off[N_NODES] = N_EDGES;
}

__global__ void k_scan3() {
    int idx = blockIdx.x * 256 + threadIdx.x;
    if (idx < N_NODES) {
        int v = g_off[idx] + g_bsum[blockIdx.x];
        g_off[idx] = v;
        g_cnt[idx] = v;  // fill cursor
    }
}

__global__ void k_fill(const int* __restrict__ src, const int* __restrict__ dst) {
    int e = blockIdx.x * blockDim.x + threadIdx.x;
    if (e < N_EDGES) {
        int pos = atomicAdd(&g_cnt[dst[e]], 1);
        g_eid[pos] = src[e];
    }
}

// ---------------- GEMM1 (tf32 HMMA): h = x @ W -> fp16, grid.y picks src/dst --------
__global__ void __launch_bounds__(256, 2)
k_gemm1(const float* __restrict__ x,
        const float* __restrict__ Wsrc, const float* __restrict__ Wdst) {
    extern __shared__ float sm[];
    float* Wsm = sm;               // [128][WPAD]
    float* xs  = sm + 128 * WPAD;  // [64][XPAD]
    const int tid = threadIdx.x;

    const float* W = blockIdx.y ? Wdst : Wsrc;
    __half* hout   = blockIdx.y ? g_hdst : g_hsrc;

    for (int i = tid; i < 128 * 32; i += 256) {
        int r = i >> 5, c4 = (i & 31) << 2;
        float4 v = ((const float4*)W)[i];
        float* p = &Wsm[r * WPAD + c4];
        p[0] = f2tf(v.x); p[1] = f2tf(v.y); p[2] = f2tf(v.z); p[3] = f2tf(v.w);
    }
    __syncthreads();

    const int warp = tid >> 5, lane = tid & 31;
    const int g = lane >> 2, t = lane & 3;
    const int m_off = (warp & 1) * 32;
    const int n_off = (warp >> 1) * 32;

    for (int r0 = blockIdx.x * 64; r0 < N_NODES; r0 += gridDim.x * 64) {
        __syncthreads();
        int rows = N_NODES - r0; if (rows > 64) rows = 64;
        for (int i = tid; i < rows * 32; i += 256) {
            int r = i >> 5, c4 = (i & 31) << 2;
            float4 v = ((const float4*)(x + (size_t)r0 * DIM))[i];
            float* p = &xs[r * XPAD + c4];
            p[0] = f2tf(v.x); p[1] = f2tf(v.y); p[2] = f2tf(v.z); p[3] = f2tf(v.w);
        }
        __syncthreads();

        float acc[2][4][4];
#pragma unroll
        for (int mt = 0; mt < 2; mt++)
#pragma unroll
            for (int j = 0; j < 4; j++)
#pragma unroll
                for (int c = 0; c < 4; c++) acc[mt][j][c] = 0.f;

#pragma unroll 4
        for (int k = 0; k < 128; k += 8) {
            unsigned a[2][4];
#pragma unroll
            for (int mt = 0; mt < 2; mt++) {
                int base = (m_off + mt * 16 + g) * XPAD + k + t;
                a[mt][0] = __float_as_uint(xs[base]);
                a[mt][1] = __float_as_uint(xs[base + 8 * XPAD]);
                a[mt][2] = __float_as_uint(xs[base + 4]);
                a[mt][3] = __float_as_uint(xs[base + 8 * XPAD + 4]);
            }
#pragma unroll
            for (int j = 0; j < 4; j++) {
                int n = n_off + 8 * j + g;
                unsigned b0 = __float_as_uint(Wsm[(k + t) * WPAD + n]);
                unsigned b1 = __float_as_uint(Wsm[(k + t + 4) * WPAD + n]);
                mma_tf32(acc[0][j], a[0], b0, b1);
                mma_tf32(acc[1][j], a[1], b0, b1);
            }
        }

#pragma unroll
        for (int mt = 0; mt < 2; mt++) {
            int rl = m_off + mt * 16 + g;
#pragma unroll
            for (int j = 0; j < 4; j++) {
                int n = n_off + 8 * j + 2 * t;
                if (rl < rows)
                    *(__half2*)&hout[(size_t)(r0 + rl) * DIM + n] =
                        __floats2half2_rn(acc[mt][j][0], acc[mt][j][1]);
                if (rl + 8 < rows)
                    *(__half2*)&hout[(size_t)(r0 + rl + 8) * DIM + n] =
                        __floats2half2_rn(acc[mt][j][2], acc[mt][j][3]);
            }
        }
    }
}

// ---------------- node-centric aggregate: one warp per dst node ----------------
// h_dst + running denom live in registers; per edge read only h_src (fp16, 256B).
// writes normalized, tf32-rounded message -> k_out GEMM consumes it directly.
__global__ void k_agg(const float* __restrict__ attn) {
    int node = (blockIdx.x * blockDim.x + threadIdx.x) >> 5;
    if (node >= N_NODES) return;
    int lane = threadIdx.x & 31;

    uint2 hdr = *(const uint2*)&g_hdst[(size_t)node * DIM + 4 * lane];
    float2 hd01 = __half22float2(*(__half2*)&hdr.x);
    float2 hd23 = __half22float2(*(__half2*)&hdr.y);
    float4 w = ((const float4*)attn)[lane];

    int beg = g_off[node], end = g_off[node + 1];
    float4 acc = make_float4(0.f, 0.f, 0.f, 0.f);
    float esum = 0.f;

    for (int i = beg; i < end; i++) {
        int s = g_eid[i];
        uint2 hsr = *(const uint2*)&g_hsrc[(size_t)s * DIM + 4 * lane];
        float2 a01 = __half22float2(*(__half2*)&hsr.x);
        float2 a23 = __half22float2(*(__half2*)&hsr.y);

        float p = lrelu(a01.x + hd01.x) * w.x + lrelu(a01.y + hd01.y) * w.y +
                  lrelu(a23.x + hd23.x) * w.z + lrelu(a23.y + hd23.y) * w.w;
        p += __shfl_xor_sync(0xFFFFFFFFu, p, 1);
        p += __shfl_xor_sync(0xFFFFFFFFu, p, 2);
        float e = __expf(p);

        acc.x += a01.x * e; acc.y += a01.y * e;
        acc.z += a23.x * e; acc.w += a23.y * e;
        esum += e;
    }

    float inv = 1.f / (esum + 1e-8f);
    float4 m;
    m.x = f2tf(acc.x * inv); m.y = f2tf(acc.y * inv);
    m.z = f2tf(acc.z * inv); m.w = f2tf(acc.w * inv);
    ((float4*)g_msg)[(size_t)node * 32 + lane] = m;
}

// ---------------- GEMM2 (tf32 HMMA) + bias + residual + LayerNorm ----------------
__global__ void __launch_bounds__(256, 2)
k_out(const float* __restrict__ Wout, const float* __restrict__ bias,
      const float* __restrict__ x, const float* __restrict__ gamma,
      const float* __restrict__ beta, float* __restrict__ out) {
    extern __shared__ float sm[];
    float* Wsm = sm;               // [128][WPAD]
    float* xs  = sm + 128 * WPAD;  // [64][XPAD], reused for result tile
    const int tid = threadIdx.x;

    for (int i = tid; i < 128 * 32; i += 256) {
        int r = i >> 5, c4 = (i & 31) << 2;
        float4 v = ((const float4*)Wout)[i];
        float* p = &Wsm[r * WPAD + c4];
        p[0] = f2tf(v.x); p[1] = f2tf(v.y); p[2] = f2tf(v.z); p[3] = f2tf(v.w);
    }
    __syncthreads();

    const int warp = tid >> 5, lane = tid & 31;
    const int g = lane >> 2, t = lane & 3;
    const int m_off = (warp & 1) * 32;
    const int n_off = (warp >> 1) * 32;

    for (int r0 = blockIdx.x * 64; r0 < N_NODES; r0 += gridDim.x * 64) {
        __syncthreads();
        int rows = N_NODES - r0; if (rows > 64) rows = 64;
        // stage messages (already normalized + tf32-rounded)
        for (int i = tid; i < rows * 32; i += 256) {
            int r = i >> 5, c4 = (i & 31) << 2;
            float4 v = ((const float4*)(g_msg + (size_t)r0 * DIM))[i];
            *(float4*)&xs[r * XPAD + c4] = v;
        }
        __syncthreads();

        float acc[2][4][4];
#pragma unroll
        for (int mt = 0; mt < 2; mt++)
#pragma unroll
            for (int j = 0; j < 4; j++)
#pragma unroll
                for (int c = 0; c < 4; c++) acc[mt][j][c] = 0.f;

#pragma unroll 4
        for (int k = 0; k < 128; k += 8) {
            unsigned a[2][4];
#pragma unroll
            for (int mt = 0; mt < 2; mt++) {
                int base = (m_off + mt * 16 + g) * XPAD + k + t;
                a[mt][0] = __float_as_uint(xs[base]);
                a[mt][1] = __float_as_uint(xs[base + 8 * XPAD]);
                a[mt][2] = __float_as_uint(xs[base + 4]);
                a[mt][3] = __float_as_uint(xs[base + 8 * XPAD + 4]);
            }
#pragma unroll
            for (int j = 0; j < 4; j++) {
                int n = n_off + 8 * j + g;
                unsigned b0 = __float_as_uint(Wsm[(k + t) * WPAD + n]);
                unsigned b1 = __float_as_uint(Wsm[(k + t + 4) * WPAD + n]);
                mma_tf32(acc[0][j], a[0], b0, b1);
                mma_tf32(acc[1][j], a[1], b0, b1);
            }
        }
        __syncthreads();  // xs readers done; reuse xs for result tile

#pragma unroll
        for (int mt = 0; mt < 2; mt++) {
            int rl = m_off + mt * 16 + g;
#pragma unroll
            for (int j = 0; j < 4; j++) {
                int n = n_off + 8 * j + 2 * t;
                xs[rl * XPAD + n]           = acc[mt][j][0];
                xs[rl * XPAD + n + 1]       = acc[mt][j][1];
                xs[(rl + 8) * XPAD + n]     = acc[mt][j][2];
                xs[(rl + 8) * XPAD + n + 1] = acc[mt][j][3];
            }
        }
        __syncthreads();

        // LN pass: 4 threads per row, 32 cols each
        {
            int row = tid >> 2, tr = tid & 3;
            if (row < rows) {
                size_t gr = (size_t)(r0 + row);
                float vals[8][4];
                float sum = 0.f, sq = 0.f;
#pragma unroll
                for (int c = 0; c < 8; c++) {
                    int col = tr * 32 + 4 * c;
                    float4 b4 = *((const float4*)&bias[col]);
                    float4 xr = *((const float4*)&x[gr * DIM + col]);
                    float* p = &xs[row * XPAD + col];
                    float v0 = p[0] + b4.x + xr.x;
                    float v1 = p[1] + b4.y + xr.y;
                    float v2 = p[2] + b4.z + xr.z;
                    float v3 = p[3] + b4.w + xr.w;
                    vals[c][0] = v0; vals[c][1] = v1; vals[c][2] = v2; vals[c][3] = v3;
                    sum += v0 + v1 + v2 + v3;
                    sq  += v0 * v0 + v1 * v1 + v2 * v2 + v3 * v3;
                }
                sum += __shfl_xor_sync(0xFFFFFFFFu, sum, 1);
                sum += __shfl_xor_sync(0xFFFFFFFFu, sum, 2);
                sq  += __shfl_xor_sync(0xFFFFFFFFu, sq, 1);
                sq  += __shfl_xor_sync(0xFFFFFFFFu, sq, 2);
                float mean = sum * (1.f / 128.f);
                float var  = sq * (1.f / 128.f) - mean * mean;
                float rstd = rsqrtf(var + 1e-5f);
#pragma unroll
                for (int c = 0; c < 8; c++) {
                    int col = tr * 32 + 4 * c;
                    float4 g4  = *((const float4*)&gamma[col]);
                    float4 be4 = *((const float4*)&beta[col]);
                    float4 o4;
                    o4.x = (vals[c][0] - mean) * rstd * g4.x + be4.x;
                    o4.y = (vals[c][1] - mean) * rstd * g4.y + be4.y;
                    o4.z = (vals[c][2] - mean) * rstd * g4.z + be4.z;
                    o4.w = (vals[c][3] - mean) * rstd * g4.w + be4.w;
                    *((float4*)&out[gr * DIM + col]) = o4;
                }
            }
        }
    }
}

// ---------------- launch ----------------
extern "C" void kernel_launch(void* const* d_in, const int* in_sizes, int n_in,
                              void* d_out, int out_size) {
    const float* x     = (const float*)d_in[0];
    const int*   ei    = (const int*)d_in[1];
    const float* Wsrc  = (const float*)d_in[2];
    const float* Wdst  = (const float*)d_in[3];
    const float* attn  = (const float*)d_in[4];
    const float* Wout  = (const float*)d_in[5];
    const float* bias  = (const float*)d_in[6];
    const float* gamma = (const float*)d_in[7];
    const float* beta  = (const float*)d_in[8];
    float* out = (float*)d_out;
    const int* src = ei;
    const int* dst = ei + N_EDGES;

    const int SMEM = (128 * WPAD + 64 * XPAD) * 4;  // ~103 KB

    cudaFuncSetAttribute(k_gemm1, cudaFuncAttributeMaxDynamicSharedMemorySize, SMEM);
    cudaFuncSetAttribute(k_out,   cudaFuncAttributeMaxDynamicSharedMemorySize, SMEM);

    const int TILES = (N_NODES + 63) / 64;  // 782
    const int EBLK  = (N_EDGES + 255) / 256;

    // CSR build (independent of gemm1)
    k_zero <<<SCAN_BLOCKS, 256>>>();
    k_hist <<<EBLK, 256>>>(dst);
    k_scan1<<<SCAN_BLOCKS, 256>>>();
    k_scan2<<<1, 256>>>();
    k_scan3<<<SCAN_BLOCKS, 256>>>();
    k_fill <<<EBLK, 256>>>(src, dst);

    // node transforms -> fp16
    k_gemm1<<<dim3(TILES, 2), 256, SMEM>>>(x, Wsrc, Wdst);

    // gather-aggregate (one warp per node)
    k_agg<<<(N_NODES * 32 + 255) / 256, 256>>>(attn);

    // output GEMM + residual + LN
    k_out<<<TILES, 256, SMEM>>>(Wout, bias, x, gamma, beta, out);
}